// round 1
// baseline (speedup 1.0000x reference)
#include <cuda_runtime.h>
#include <cuda_bf16.h>

#define MAX_M 128
#define INV_TWO_PI 0.15915494309189535f

// One warp per attention row n. Lanes stride over the M basis functions, so
// stores to out[n*M + j] are fully coalesced across the warp.
__global__ __launch_bounds__(256) void ContinuousSoftmax_kernel(
    const float* __restrict__ theta,        // [N,6]
    const float* __restrict__ basis_mu,     // [M,2]
    const float* __restrict__ basis_sigma,  // [M,2,2] (symmetric)
    float* __restrict__ out,                // [N,M]
    int N, int M)
{
    __shared__ float bm0[MAX_M], bm1[MAX_M];
    __shared__ float bs00[MAX_M], bs01[MAX_M], bs11[MAX_M];

    // Stage basis parameters once per block.
    for (int j = threadIdx.x; j < M; j += blockDim.x) {
        bm0[j]  = basis_mu[2 * j + 0];
        bm1[j]  = basis_mu[2 * j + 1];
        bs00[j] = basis_sigma[4 * j + 0];
        bs01[j] = basis_sigma[4 * j + 1];
        bs11[j] = basis_sigma[4 * j + 3];
    }
    __syncthreads();

    const int warp = threadIdx.x >> 5;
    const int lane = threadIdx.x & 31;
    const int n = blockIdx.x * (blockDim.x >> 5) + warp;
    if (n >= N) return;

    // theta row: 6 floats, 8B-aligned -> 3x LDG.64 broadcast within the warp.
    const float2* th = reinterpret_cast<const float2*>(theta) + (size_t)n * 3;
    const float2 e  = th[0];  // t0, t1  (eta)
    const float2 q0 = th[1];  // t2, t3
    const float2 q1 = th[2];  // t4, t5
    // P = -2 * [[t2,t3],[t4,t5]], detP = 4*(t2*t5 - t3*t4)
    // Sigma = 0.5*(Pinv + Pinv^T):
    //   s00 = -t5/(2d), s11 = -t2/(2d), s01 = (t3+t4)/(4d),  d = t2*t5 - t3*t4
    const float d   = q0.x * q1.y - q0.y * q1.x;
    const float inv = __fdividef(1.0f, 2.0f * d);
    const float s00 = -q1.y * inv;
    const float s11 = -q0.x * inv;
    const float s01 = 0.5f * (q0.y + q1.x) * inv;
    const float mu0 = s00 * e.x + s01 * e.y;
    const float mu1 = s01 * e.x + s11 * e.y;

    float* orow = out + (size_t)n * M;
    #pragma unroll 4
    for (int j = lane; j < M; j += 32) {
        const float c00 = s00 + bs00[j];
        const float c01 = s01 + bs01[j];
        const float c11 = s11 + bs11[j];
        const float dx  = mu0 - bm0[j];
        const float dy  = mu1 - bm1[j];
        const float det = c00 * c11 - c01 * c01;
        // quad = (c11*dx^2 - 2*c01*dx*dy + c00*dy^2) / det
        const float num = c11 * dx * dx - 2.0f * c01 * dx * dy + c00 * dy * dy;
        const float rs  = rsqrtf(det);        // MUFU.RSQ
        const float invdet = rs * rs;         // 1/det on FMA pipe (no extra MUFU)
        orow[j] = __expf(-0.5f * num * invdet) * (INV_TWO_PI * rs);  // MUFU.EX2
    }
}

extern "C" void kernel_launch(void* const* d_in, const int* in_sizes, int n_in,
                              void* d_out, int out_size) {
    const float* theta       = (const float*)d_in[0];
    const float* basis_mu    = (const float*)d_in[1];
    const float* basis_sigma = (const float*)d_in[2];
    float* out = (float*)d_out;

    const int N = in_sizes[0] / 6;
    const int M = in_sizes[1] / 2;

    const int threads = 256;
    const int rows_per_block = threads / 32;
    const int blocks = (N + rows_per_block - 1) / rows_per_block;
    ContinuousSoftmax_kernel<<<blocks, threads>>>(theta, basis_mu, basis_sigma,
                                                  out, N, M);
}

// round 2
// speedup vs baseline: 2.1110x; 2.1110x over previous
#include <cuda_runtime.h>
#include <cuda_bf16.h>

#define M_CONST   100
#define GROUPS    25      // M/4 float4 groups per row
#define ROWS_ITER 10      // rows handled per block iteration (250 active threads)
#define ACTIVE    (GROUPS * ROWS_ITER)
#define INV_TWO_PI 0.15915494309189535f

// Thread t (t<250): owns basis group g = t%25 (j = 4g..4g+3, cached in registers)
// and local row slot r = t/25. Grid-strides over rows in chunks of 10 per block.
// One STG.128 per row per thread; no shared memory, no syncs.
__global__ __launch_bounds__(256) void ContinuousSoftmax_kernel(
    const float* __restrict__ theta,        // [N,6]
    const float* __restrict__ basis_mu,     // [M,2]
    const float* __restrict__ basis_sigma,  // [M,2,2] symmetric
    float* __restrict__ out,                // [N,M]
    int N)
{
    const int tid = threadIdx.x;
    if (tid >= ACTIVE) return;
    const int r_local = tid / GROUPS;
    const int g       = tid - r_local * GROUPS;   // 0..24

    // ---- one-time: load this thread's 4 basis entries into registers ----
    const float4* bm = reinterpret_cast<const float4*>(basis_mu) + 2 * g;
    const float4  m01 = bm[0];      // (mu0_j0, mu1_j0, mu0_j1, mu1_j1)
    const float4  m23 = bm[1];
    const float4* bs = reinterpret_cast<const float4*>(basis_sigma) + 4 * g;
    const float4  sg0 = bs[0], sg1 = bs[1], sg2 = bs[2], sg3 = bs[3];

    const float bm0[4] = {m01.x, m01.z, m23.x, m23.z};
    const float bm1[4] = {m01.y, m01.w, m23.y, m23.w};
    const float b00[4] = {sg0.x, sg1.x, sg2.x, sg3.x};
    const float b01[4] = {sg0.y, sg1.y, sg2.y, sg3.y};
    const float b11[4] = {sg0.w, sg1.w, sg2.w, sg3.w};

    const int stride = gridDim.x * ROWS_ITER;
    for (int base = blockIdx.x * ROWS_ITER; base < N; base += stride) {
        const int n = base + r_local;
        if (n >= N) break;

        // theta row: 3x LDG.64 (broadcast among the ~25 threads sharing n)
        const float2* th = reinterpret_cast<const float2*>(theta) + (size_t)n * 3;
        const float2 e  = th[0];
        const float2 q0 = th[1];
        const float2 q1 = th[2];

        // Sigma = 0.5*(Pinv + Pinv^T) with P = -2*[[q0.x,q0.y],[q1.x,q1.y]]
        const float d   = q0.x * q1.y - q0.y * q1.x;
        const float inv = __fdividef(-0.5f, d);           // MUFU.RCP + mul
        const float s00 = q1.y * inv;
        const float s11 = q0.x * inv;
        const float s01 = -0.5f * (q0.y + q1.x) * inv;
        const float mu0 = s00 * e.x + s01 * e.y;
        const float mu1 = s01 * e.x + s11 * e.y;

        float res[4];
        #pragma unroll
        for (int k = 0; k < 4; ++k) {
            const float c00 = s00 + b00[k];
            const float c01 = s01 + b01[k];
            const float c11 = s11 + b11[k];
            const float dx  = mu0 - bm0[k];
            const float dy  = mu1 - bm1[k];
            const float det = c00 * c11 - c01 * c01;
            const float xx  = dx * dx;
            const float yy  = dy * dy;
            const float xy2 = 2.0f * (dx * dy);
            float num = c11 * xx;
            num = fmaf(c00, yy, num);
            num = fmaf(-c01, xy2, num);
            const float rs  = rsqrtf(det);                // MUFU.RSQ
            const float arg = num * (-0.5f * rs * rs);
            res[k] = __expf(arg) * (INV_TWO_PI * rs);     // FMUL+MUFU.EX2, FMULs
        }
        float4 v = make_float4(res[0], res[1], res[2], res[3]);
        *reinterpret_cast<float4*>(out + (size_t)n * M_CONST + 4 * g) = v;
    }
}

extern "C" void kernel_launch(void* const* d_in, const int* in_sizes, int n_in,
                              void* d_out, int out_size) {
    const float* theta       = (const float*)d_in[0];
    const float* basis_mu    = (const float*)d_in[1];
    const float* basis_sigma = (const float*)d_in[2];
    float* out = (float*)d_out;

    const int N = in_sizes[0] / 6;

    const int threads = 256;
    const int needed  = (N + ROWS_ITER - 1) / ROWS_ITER;  // block-iterations
    int blocks = 1536;                                    // persistent-ish grid
    if (blocks > needed) blocks = needed;
    ContinuousSoftmax_kernel<<<blocks, threads>>>(theta, basis_mu, basis_sigma,
                                                  out, N);
}

// round 3
// speedup vs baseline: 2.2521x; 1.0669x over previous
#include <cuda_runtime.h>
#include <cuda_bf16.h>
#include <cstdint>

#define M_CONST   100
#define GROUPS    25      // M/4 float4 groups per row
#define ROWS_ITER 10      // rows per block iteration (250 active threads)
#define ACTIVE    (GROUPS * ROWS_ITER)

// ---- packed f32x2 helpers (sm_103a: FFMA2/FADD2/FMUL2 via PTX f32x2) ----
__device__ __forceinline__ uint64_t pk2(float lo, float hi) {
    uint64_t r; asm("mov.b64 %0, {%1,%2};" : "=l"(r) : "f"(lo), "f"(hi)); return r;
}
__device__ __forceinline__ void upk2(uint64_t v, float& lo, float& hi) {
    asm("mov.b64 {%0,%1}, %2;" : "=f"(lo), "=f"(hi) : "l"(v));
}
__device__ __forceinline__ uint64_t fma2_(uint64_t a, uint64_t b, uint64_t c) {
    uint64_t d; asm("fma.rn.f32x2 %0,%1,%2,%3;" : "=l"(d) : "l"(a), "l"(b), "l"(c)); return d;
}
__device__ __forceinline__ uint64_t add2_(uint64_t a, uint64_t b) {
    uint64_t d; asm("add.rn.f32x2 %0,%1,%2;" : "=l"(d) : "l"(a), "l"(b)); return d;
}
__device__ __forceinline__ uint64_t mul2_(uint64_t a, uint64_t b) {
    uint64_t d; asm("mul.rn.f32x2 %0,%1,%2;" : "=l"(d) : "l"(a), "l"(b)); return d;
}
__device__ __forceinline__ uint64_t neg2_(uint64_t a) {   // sign-flip both lanes (ALU pipe)
    return a ^ 0x8000000080000000ULL;
}
__device__ __forceinline__ float ex2_(float x) {
    float r; asm("ex2.approx.f32 %0, %1;" : "=f"(r) : "f"(x)); return r;
}

// -0.5 * log2(e): folds the exp() base change into the packed arg multiply.
#define NEG_HALF_LOG2E -0.7213475204444817f
#define INV_TWO_PI      0.15915494309189535f

// Thread t (<250): owns basis group g = t%25 (elements 4g..4g+3 as two f32x2
// lanes, cached in registers) and row slot r = t/25. Grid-strides over rows.
// One STG.128 per row per thread; no shared memory, no syncs.
__global__ __launch_bounds__(256) void ContinuousSoftmax_kernel(
    const float* __restrict__ theta,        // [N,6]
    const float* __restrict__ basis_mu,     // [M,2]
    const float* __restrict__ basis_sigma,  // [M,2,2] symmetric
    float* __restrict__ out,                // [N,M]
    int N)
{
    const int tid = threadIdx.x;
    if (tid >= ACTIVE) return;
    const int r_local = tid / GROUPS;
    const int g       = tid - r_local * GROUPS;   // 0..24

    // ---- one-time: load this thread's 4 basis entries, pack per element-pair ----
    const float4* bm = reinterpret_cast<const float4*>(basis_mu) + 2 * g;
    const float4  m01 = bm[0];      // (mu0_j0, mu1_j0, mu0_j1, mu1_j1)
    const float4  m23 = bm[1];
    const float4* bs = reinterpret_cast<const float4*>(basis_sigma) + 4 * g;
    const float4  sg0 = bs[0], sg1 = bs[1], sg2 = bs[2], sg3 = bs[3];

    uint64_t nbm0[2], nbm1[2], b00[2], b01[2], b11[2];
    nbm0[0] = pk2(-m01.x, -m01.z);  nbm0[1] = pk2(-m23.x, -m23.z);
    nbm1[0] = pk2(-m01.y, -m01.w);  nbm1[1] = pk2(-m23.y, -m23.w);
    b00[0]  = pk2(sg0.x, sg1.x);    b00[1]  = pk2(sg2.x, sg3.x);
    b01[0]  = pk2(sg0.y, sg1.y);    b01[1]  = pk2(sg2.y, sg3.y);
    b11[0]  = pk2(sg0.w, sg1.w);    b11[1]  = pk2(sg2.w, sg3.w);

    const uint64_t cArg  = pk2(NEG_HALF_LOG2E, NEG_HALF_LOG2E);
    const uint64_t cItp  = pk2(INV_TWO_PI, INV_TWO_PI);

    const int stride = gridDim.x * ROWS_ITER;
    for (int base = blockIdx.x * ROWS_ITER; base < N; base += stride) {
        const int n = base + r_local;
        if (n >= N) break;

        // theta row: 3x LDG.64 (L1-broadcast among the 25 threads sharing n)
        const float2* th = reinterpret_cast<const float2*>(theta) + (size_t)n * 3;
        const float2 e  = th[0];
        const float2 q0 = th[1];
        const float2 q1 = th[2];

        // Sigma = 0.5*(Pinv + Pinv^T), P = -2*[[q0.x,q0.y],[q1.x,q1.y]]
        const float d   = q0.x * q1.y - q0.y * q1.x;
        const float inv = __fdividef(-0.5f, d);
        const float s00 = q1.y * inv;
        const float s11 = q0.x * inv;
        const float s01 = -0.5f * (q0.y + q1.x) * inv;
        const float mu0 = s00 * e.x + s01 * e.y;
        const float mu1 = s01 * e.x + s11 * e.y;

        const uint64_t s00v = pk2(s00, s00);
        const uint64_t s01v = pk2(s01, s01);
        const uint64_t s11v = pk2(s11, s11);
        const uint64_t mu0v = pk2(mu0, mu0);
        const uint64_t mu1v = pk2(mu1, mu1);

        float res[4];
        #pragma unroll
        for (int p = 0; p < 2; ++p) {
            const uint64_t c00  = add2_(s00v, b00[p]);
            const uint64_t c01  = add2_(s01v, b01[p]);
            const uint64_t c11  = add2_(s11v, b11[p]);
            const uint64_t dx   = add2_(mu0v, nbm0[p]);
            const uint64_t dy   = add2_(mu1v, nbm1[p]);
            const uint64_t nc01 = neg2_(c01);                       // ALU
            const uint64_t det  = fma2_(nc01, c01, mul2_(c00, c11));
            const uint64_t xx   = mul2_(dx, dx);
            const uint64_t yy   = mul2_(dy, dy);
            const uint64_t dxy  = mul2_(dx, dy);
            const uint64_t dxy2 = add2_(dxy, dxy);
            uint64_t num = mul2_(c11, xx);
            num = fma2_(c00, yy, num);
            num = fma2_(nc01, dxy2, num);

            float d0, d1; upk2(det, d0, d1);
            const float r0 = rsqrtf(d0);                            // MUFU.RSQ
            const float r1 = rsqrtf(d1);
            const uint64_t rsv  = pk2(r0, r1);
            const uint64_t idet = mul2_(rsv, rsv);                  // 1/det
            const uint64_t argv = mul2_(mul2_(num, idet), cArg);    // -.5*log2e*quad
            float a0, a1; upk2(argv, a0, a1);
            const float e0 = ex2_(a0);                              // MUFU.EX2
            const float e1 = ex2_(a1);
            const uint64_t scl = mul2_(rsv, cItp);                  // rs/(2pi)
            const uint64_t rv  = mul2_(pk2(e0, e1), scl);
            upk2(rv, res[2 * p], res[2 * p + 1]);
        }
        float4 v = make_float4(res[0], res[1], res[2], res[3]);
        *reinterpret_cast<float4*>(out + (size_t)n * M_CONST + 4 * g) = v;
    }
}

extern "C" void kernel_launch(void* const* d_in, const int* in_sizes, int n_in,
                              void* d_out, int out_size) {
    const float* theta       = (const float*)d_in[0];
    const float* basis_mu    = (const float*)d_in[1];
    const float* basis_sigma = (const float*)d_in[2];
    float* out = (float*)d_out;

    const int N = in_sizes[0] / 6;

    const int threads = 256;
    const int needed  = (N + ROWS_ITER - 1) / ROWS_ITER;
    int blocks = 1536;
    if (blocks > needed) blocks = needed;
    ContinuousSoftmax_kernel<<<blocks, threads>>>(theta, basis_mu, basis_sigma,
                                                  out, N);
}